// round 2
// baseline (speedup 1.0000x reference)
#include <cuda_runtime.h>
#include <math.h>
#include <stdint.h>

#define BB 32
#define GG 64
#define NN 4096
#define CC 384
#define SCALE 0.051031036307982884f  /* 384^-0.5 */

// ---------------- scratch (device globals; no allocation allowed) ----------------
__device__ float g_Wq[CC*CC];        // q_w.T @ k_w
__device__ float g_Mm[CC*CC];        // p_w @ v_w
__device__ float g_bq2[CC];          // q_b @ k_w
__device__ float g_u[CC];            // q_w.T @ k_b
__device__ float g_pvb[CC];          // p_w @ v_b
__device__ float g_s0[1];            // q_b . k_b
__device__ float g_q2[BB*GG*CC];     // query @ Wq + bq2
__device__ float g_t[BB*GG];         // per (b,g) bias
__device__ int   g_idx[BB*NN];       // argmax group per (b,n)
__device__ int   g_cnt[BB*GG];       // counts per (b,g)
__device__ float g_Sp[4*BB*GG*CC];   // 4 n-segment partial key sums

// ---------------- f32x2 packed helpers (sm_103a) ----------------
__device__ __forceinline__ void fma_f32x2(unsigned long long& d, unsigned long long a,
                                          unsigned long long b, unsigned long long c) {
    asm("fma.rn.f32x2 %0, %1, %2, %3;" : "=l"(d) : "l"(a), "l"(b), "l"(c));
}
__device__ __forceinline__ unsigned long long pack2(float lo, float hi) {
    unsigned long long d;
    asm("mov.b64 %0, {%1, %2};" : "=l"(d) : "f"(lo), "f"(hi));
    return d;
}
__device__ __forceinline__ void unpack2(float& lo, float& hi, unsigned long long v) {
    asm("mov.b64 {%0, %1}, %2;" : "=f"(lo), "=f"(hi) : "l"(v));
}

// ---------------- zero counts ----------------
__global__ void k_zero(int* cnt) {
    int t = blockIdx.x * blockDim.x + threadIdx.x;
    if (t < BB*GG) cnt[t] = 0;
}

// ---------------- generic 64x64-tile fp32 GEMM (K=C=384, N mult of 64) ----------------
// AM: 0 = A row-major A[i*C+k]; 1 = A k-major A[k*C+i]; 2 = row-major sum of 4 partials
// BM: 0 = B k-major B[k*C+j];   1 = B n-major B[j*C+k]
// EPI:0 = store; 1 = +bias[j]; 2 = out epilogue ((v+cnt*pvb)/(cnt+1)+bias)
template<int AM, int BM, int EPI>
__global__ void __launch_bounds__(256) k_gemm64(const float* __restrict__ A,
                                                const float* __restrict__ Bm,
                                                float* __restrict__ Cc,
                                                const float* __restrict__ bias,
                                                const int* __restrict__ cnt,
                                                const float* __restrict__ pvb) {
    __shared__ float As[16][68];
    __shared__ float Bs[16][68];
    int j0 = blockIdx.x * 64, i0 = blockIdx.y * 64;
    int tid = threadIdx.x;
    float acc[4][4] = {};
    for (int k0 = 0; k0 < CC; k0 += 16) {
        // --- A tile: 64 i x 16 k ---
        if (AM == 1) {
            int kk = tid >> 4, i4 = (tid & 15) * 4;
            *(float4*)&As[kk][i4] = *(const float4*)&A[(size_t)(k0 + kk) * CC + i0 + i4];
        } else {
            int r = tid >> 2, kq = (tid & 3) * 4;
            float4 v;
            if (AM == 2) {
                const float* p = &A[(size_t)(i0 + r) * CC + k0 + kq];
                const size_t PS = (size_t)BB * GG * CC;
                float4 v0 = *(const float4*)p;
                float4 v1 = *(const float4*)(p + PS);
                float4 v2 = *(const float4*)(p + 2 * PS);
                float4 v3 = *(const float4*)(p + 3 * PS);
                v.x = v0.x + v1.x + v2.x + v3.x;
                v.y = v0.y + v1.y + v2.y + v3.y;
                v.z = v0.z + v1.z + v2.z + v3.z;
                v.w = v0.w + v1.w + v2.w + v3.w;
            } else {
                v = *(const float4*)&A[(size_t)(i0 + r) * CC + k0 + kq];
            }
            As[kq + 0][r] = v.x; As[kq + 1][r] = v.y;
            As[kq + 2][r] = v.z; As[kq + 3][r] = v.w;
        }
        // --- B tile: 16 k x 64 j ---
        if (BM == 0) {
            int kk = tid >> 4, j4 = (tid & 15) * 4;
            *(float4*)&Bs[kk][j4] = *(const float4*)&Bm[(size_t)(k0 + kk) * CC + j0 + j4];
        } else {
            int jr = tid >> 2, kq = (tid & 3) * 4;
            float4 v = *(const float4*)&Bm[(size_t)(j0 + jr) * CC + k0 + kq];
            Bs[kq + 0][jr] = v.x; Bs[kq + 1][jr] = v.y;
            Bs[kq + 2][jr] = v.z; Bs[kq + 3][jr] = v.w;
        }
        __syncthreads();
        int ty = tid >> 4, tx = tid & 15;
        #pragma unroll
        for (int kk = 0; kk < 16; kk++) {
            float4 a4 = *(const float4*)&As[kk][ty * 4];
            float4 b4 = *(const float4*)&Bs[kk][tx * 4];
            float av[4] = {a4.x, a4.y, a4.z, a4.w};
            float bv[4] = {b4.x, b4.y, b4.z, b4.w};
            #pragma unroll
            for (int i = 0; i < 4; i++)
                #pragma unroll
                for (int j = 0; j < 4; j++)
                    acc[i][j] += av[i] * bv[j];
        }
        __syncthreads();
    }
    int ty = tid >> 4, tx = tid & 15;
    #pragma unroll
    for (int i = 0; i < 4; i++) {
        int r = i0 + ty * 4 + i;
        #pragma unroll
        for (int j = 0; j < 4; j++) {
            int c = j0 + tx * 4 + j;
            float v = acc[i][j];
            if (EPI == 1) v += bias[c];
            if (EPI == 2) {
                float cf = (float)cnt[r];
                v = (v + cf * pvb[c]) / (cf + 1.0f) + bias[c];
            }
            Cc[(size_t)r * CC + c] = v;
        }
    }
}

// ---------------- tiny vector precomputes ----------------
__global__ void k_prep_vecs(const float* __restrict__ qw, const float* __restrict__ qb,
                            const float* __restrict__ kw, const float* __restrict__ kb,
                            const float* __restrict__ pw, const float* __restrict__ vb) {
    int j = threadIdx.x;  // 384
    float b2 = 0.f, u = 0.f, pv = 0.f;
    for (int c = 0; c < CC; c++) {
        b2 += qb[c] * kw[(size_t)c * CC + j];
        u  += qw[(size_t)c * CC + j] * kb[c];
        pv += pw[(size_t)j * CC + c] * vb[c];
    }
    g_bq2[j] = b2; g_u[j] = u; g_pvb[j] = pv;
    if (j == 0) {
        float s = 0.f;
        for (int c = 0; c < CC; c++) s += qb[c] * kb[c];
        g_s0[0] = s;
    }
}

// ---------------- t[r] = query[r,:].u + s0 ----------------
__global__ void k_t(const float* __restrict__ query) {
    int r = blockIdx.x * 8 + threadIdx.y;
    int lane = threadIdx.x;
    float s = 0.f;
    for (int c = lane; c < CC; c += 32) s += query[(size_t)r * CC + c] * g_u[c];
    #pragma unroll
    for (int o = 16; o; o >>= 1) s += __shfl_xor_sync(0xFFFFFFFFu, s, o);
    if (lane == 0) g_t[r] = s + g_s0[0];
}

// ---------------- logits: L[b,g,n] = SCALE*(q2[b,g,:].key[b,n,:] + t[b,g]) ----------------
// 64(g) x 128(n) tile per block; 128 threads; 8x8 micro-tile; packed f32x2 FMA.
__global__ void __launch_bounds__(128) k_logits(const float* __restrict__ key,
                                                float* __restrict__ soft) {
    __shared__ float sA[16][72];
    __shared__ float sB[16][136];
    int b = blockIdx.y;
    int n_base = blockIdx.x * 128;
    int tid = threadIdx.x;
    const float* q2 = g_q2 + (size_t)b * GG * CC;
    const float* kp = key + ((size_t)b * NN + n_base) * CC;
    unsigned long long acc2[8][4];
    #pragma unroll
    for (int i = 0; i < 8; i++)
        #pragma unroll
        for (int j = 0; j < 4; j++) acc2[i][j] = 0ULL;

    for (int k0 = 0; k0 < CC; k0 += 16) {
        {   // A: 64g x 16k  (8 floats / thread)
            int g = tid >> 1, ks = (tid & 1) * 8;
            float4 v0 = *(const float4*)&q2[(size_t)g * CC + k0 + ks];
            float4 v1 = *(const float4*)&q2[(size_t)g * CC + k0 + ks + 4];
            sA[ks + 0][g] = v0.x; sA[ks + 1][g] = v0.y; sA[ks + 2][g] = v0.z; sA[ks + 3][g] = v0.w;
            sA[ks + 4][g] = v1.x; sA[ks + 5][g] = v1.y; sA[ks + 6][g] = v1.z; sA[ks + 7][g] = v1.w;
        }
        #pragma unroll
        for (int p = 0; p < 4; p++) {  // B: 128n x 16k (4 float4 / thread)
            int nn = (tid >> 2) + p * 32, kq = (tid & 3) * 4;
            float4 v = *(const float4*)&kp[(size_t)nn * CC + k0 + kq];
            sB[kq + 0][nn] = v.x; sB[kq + 1][nn] = v.y;
            sB[kq + 2][nn] = v.z; sB[kq + 3][nn] = v.w;
        }
        __syncthreads();
        int ty = tid >> 4, tx = tid & 15;
        #pragma unroll
        for (int kk = 0; kk < 16; kk++) {
            float a[8];
            *(float4*)&a[0] = *(const float4*)&sA[kk][ty * 8];
            *(float4*)&a[4] = *(const float4*)&sA[kk][ty * 8 + 4];
            unsigned long long b2[4];
            b2[0] = *(const unsigned long long*)&sB[kk][tx * 8 + 0];
            b2[1] = *(const unsigned long long*)&sB[kk][tx * 8 + 2];
            b2[2] = *(const unsigned long long*)&sB[kk][tx * 8 + 4];
            b2[3] = *(const unsigned long long*)&sB[kk][tx * 8 + 6];
            #pragma unroll
            for (int i = 0; i < 8; i++) {
                unsigned long long aa = pack2(a[i], a[i]);
                #pragma unroll
                for (int j = 0; j < 4; j++) fma_f32x2(acc2[i][j], aa, b2[j], acc2[i][j]);
            }
        }
        __syncthreads();
    }
    int ty = tid >> 4, tx = tid & 15;
    float* outp = soft + (size_t)b * GG * NN + n_base + tx * 8;
    #pragma unroll
    for (int i = 0; i < 8; i++) {
        int g = ty * 8 + i;
        float tb = g_t[b * GG + g];
        float o[8];
        #pragma unroll
        for (int j = 0; j < 4; j++) unpack2(o[2 * j], o[2 * j + 1], acc2[i][j]);
        #pragma unroll
        for (int j = 0; j < 8; j++) o[j] = SCALE * (o[j] + tb);
        *(float4*)&outp[(size_t)g * NN + 0] = *(float4*)&o[0];
        *(float4*)&outp[(size_t)g * NN + 4] = *(float4*)&o[4];
    }
}

// ---------------- column softmax over G, argmax, counts (in-place) ----------------
__global__ void k_softmax(float* __restrict__ soft, int* __restrict__ idx,
                          int* __restrict__ cnt) {
    int t = blockIdx.x * blockDim.x + threadIdx.x;  // over B*N
    int b = t >> 12, n = t & (NN - 1);
    float* col = soft + (size_t)b * GG * NN + n;
    float v[GG];
    float mx = -3.4e38f;
    int am = 0;
    #pragma unroll
    for (int g = 0; g < GG; g++) {
        v[g] = col[(size_t)g * NN];
        if (v[g] > mx) { mx = v[g]; am = g; }
    }
    float s = 0.f;
    #pragma unroll
    for (int g = 0; g < GG; g++) { v[g] = __expf(v[g] - mx); s += v[g]; }
    float inv = 1.0f / s;
    #pragma unroll
    for (int g = 0; g < GG; g++) col[(size_t)g * NN] = v[g] * inv;
    idx[t] = am;
    atomicAdd(&cnt[b * GG + am], 1);
}

// ---------------- segment sums of key rows by argmax group ----------------
__global__ void __launch_bounds__(128) k_seg(const float* __restrict__ key) {
    __shared__ float S[GG][128];
    __shared__ int sidx[1024];
    int ns = blockIdx.x, cb = blockIdx.y, b = blockIdx.z;
    int tid = threadIdx.x;
    int c0 = cb * 128, nb = ns * 1024;
    for (int i = tid; i < GG * 128; i += 128) ((float*)S)[i] = 0.f;
    for (int i = tid; i < 1024; i += 128) sidx[i] = g_idx[b * NN + nb + i];
    __syncthreads();
    const float* kp = key + ((size_t)(b * NN + nb)) * CC + c0;
    for (int n = 0; n < 1024; n += 4) {
        float x0 = kp[(size_t)(n + 0) * CC + tid];
        float x1 = kp[(size_t)(n + 1) * CC + tid];
        float x2 = kp[(size_t)(n + 2) * CC + tid];
        float x3 = kp[(size_t)(n + 3) * CC + tid];
        S[sidx[n + 0]][tid] += x0;
        S[sidx[n + 1]][tid] += x1;
        S[sidx[n + 2]][tid] += x2;
        S[sidx[n + 3]][tid] += x3;
    }
    __syncthreads();
    float* dst = g_Sp + (size_t)ns * BB * GG * CC + (size_t)b * GG * CC + c0 + tid;
    for (int g = 0; g < GG; g++) dst[(size_t)g * CC] = S[g][tid];
}

// ---------------- launcher ----------------
extern "C" void kernel_launch(void* const* d_in, const int* in_sizes, int n_in,
                              void* d_out, int out_size) {
    const float* query = (const float*)d_in[0];
    const float* key   = (const float*)d_in[1];
    const float* q_w   = (const float*)d_in[2];
    const float* q_b   = (const float*)d_in[3];
    const float* k_w   = (const float*)d_in[4];
    const float* k_b   = (const float*)d_in[5];
    const float* v_w   = (const float*)d_in[6];
    const float* v_b   = (const float*)d_in[7];
    const float* p_w   = (const float*)d_in[8];
    const float* p_b   = (const float*)d_in[9];
    (void)q_b; (void)k_b; (void)v_w; (void)v_b; (void)n_in; (void)in_sizes;

    float* out  = (float*)d_out;
    float* soft = out + ((size_t)out_size - (size_t)BB * GG * NN);

    float *pWq, *pMm, *pbq2, *pq2, *ppvb, *pSp;
    int *pidx, *pcnt;
    cudaGetSymbolAddress((void**)&pWq,  g_Wq);
    cudaGetSymbolAddress((void**)&pMm,  g_Mm);
    cudaGetSymbolAddress((void**)&pbq2, g_bq2);
    cudaGetSymbolAddress((void**)&pq2,  g_q2);
    cudaGetSymbolAddress((void**)&ppvb, g_pvb);
    cudaGetSymbolAddress((void**)&pSp,  g_Sp);
    cudaGetSymbolAddress((void**)&pidx, g_idx);
    cudaGetSymbolAddress((void**)&pcnt, g_cnt);

    // 1. zero counts
    k_zero<<<2, 1024>>>(pcnt);
    // 2. Wq = q_w.T @ k_w ; Mm = p_w @ v_w
    k_gemm64<1, 0, 0><<<dim3(6, 6), 256>>>(q_w, k_w, pWq, nullptr, nullptr, nullptr);
    k_gemm64<0, 0, 0><<<dim3(6, 6), 256>>>(p_w, v_w, pMm, nullptr, nullptr, nullptr);
    // 3. bias vectors
    k_prep_vecs<<<1, CC>>>(q_w, q_b, k_w, k_b, p_w, v_b);
    // 4. t[r]
    k_t<<<BB * GG / 8, dim3(32, 8)>>>(query);
    // 5. q2 = query @ Wq + bq2
    k_gemm64<0, 0, 1><<<dim3(6, 32), 256>>>(query, pWq, pq2, pbq2, nullptr, nullptr);
    // 6. logits into soft region
    k_logits<<<dim3(NN / 128, BB), 128>>>(key, soft);
    // 7. softmax over G + argmax + counts (in place)
    k_softmax<<<BB * NN / 256, 256>>>(soft, pidx, pcnt);
    // 8. segment sums of key
    k_seg<<<dim3(4, 3, BB), 128>>>(key);
    // 9. out = (S @ Mm.T + cnt*pvb)/(cnt+1) + p_b
    k_gemm64<2, 1, 2><<<dim3(6, 32), 256>>>(pSp, pMm, out, p_b, pcnt, ppvb);
}

// round 3
// speedup vs baseline: 1.2544x; 1.2544x over previous
#include <cuda_runtime.h>
#include <math.h>
#include <stdint.h>

#define BB 32
#define GG 64
#define NN 4096
#define CC 384
#define NSEG 8
#define SCALE 0.051031036307982884f  /* 384^-0.5 */

// ---------------- scratch (device globals; no allocation allowed) ----------------
__device__ float g_Wq[CC*CC];        // q_w.T @ k_w
__device__ float g_Mm[CC*CC];        // p_w @ v_w
__device__ float g_bq2[CC];          // q_b @ k_w
__device__ float g_u[CC];            // q_w.T @ k_b
__device__ float g_pvb[CC];          // p_w @ v_b
__device__ float g_s0[1];            // q_b . k_b
__device__ float g_b2p[12*CC];       // partials for bq2
__device__ float g_up[12*CC];        // partials for u
__device__ float g_q2[BB*GG*CC];     // query @ Wq + bq2
__device__ float g_t[BB*GG];         // per (b,g) bias
__device__ int   g_idx[BB*NN];       // argmax group per (b,n)
__device__ int   g_cnt[BB*GG];       // counts per (b,g)
__device__ float g_Sp[NSEG*BB*GG*CC];// n-segment partial key sums

// ---------------- f32x2 packed helpers (sm_103a) ----------------
__device__ __forceinline__ void fma_f32x2(unsigned long long& d, unsigned long long a,
                                          unsigned long long b, unsigned long long c) {
    asm("fma.rn.f32x2 %0, %1, %2, %3;" : "=l"(d) : "l"(a), "l"(b), "l"(c));
}
__device__ __forceinline__ unsigned long long pack2(float lo, float hi) {
    unsigned long long d;
    asm("mov.b64 %0, {%1, %2};" : "=l"(d) : "f"(lo), "f"(hi));
    return d;
}
__device__ __forceinline__ void unpack2(float& lo, float& hi, unsigned long long v) {
    asm("mov.b64 {%0, %1}, %2;" : "=f"(lo), "=f"(hi) : "l"(v));
}

// ---------------- zero counts ----------------
__global__ void k_zero(int* cnt) {
    int t = blockIdx.x * blockDim.x + threadIdx.x;
    if (t < BB*GG) cnt[t] = 0;
}

// ---------------- parallel precompute: column reductions (partials) ----------------
// block bc (0..11) handles c in [bc*32, bc*32+32); thread j in 0..383 (coalesced over j)
__global__ void __launch_bounds__(CC) k_prep_cols(const float* __restrict__ qw,
                                                  const float* __restrict__ qb,
                                                  const float* __restrict__ kw,
                                                  const float* __restrict__ kb) {
    int j = threadIdx.x;
    int c0 = blockIdx.x * 32;
    float b2 = 0.f, u = 0.f;
    #pragma unroll 8
    for (int c = c0; c < c0 + 32; c++) {
        b2 += qb[c] * kw[(size_t)c * CC + j];
        u  += qw[(size_t)c * CC + j] * kb[c];
    }
    g_b2p[blockIdx.x * CC + j] = b2;
    g_up [blockIdx.x * CC + j] = u;
}

// reduce 12 partials -> g_bq2, g_u (deterministic)
__global__ void k_prep_red() {
    int j = threadIdx.x;
    float b2 = 0.f, u = 0.f;
    #pragma unroll
    for (int p = 0; p < 12; p++) { b2 += g_b2p[p * CC + j]; u += g_up[p * CC + j]; }
    g_bq2[j] = b2; g_u[j] = u;
}

// pv[j] = p_w[j,:].v_b  (warp per row, coalesced within row); block 96: s0 = qb.kb
__global__ void __launch_bounds__(128) k_prep_pv(const float* __restrict__ pw,
                                                 const float* __restrict__ vb,
                                                 const float* __restrict__ qb,
                                                 const float* __restrict__ kb) {
    int w = threadIdx.x >> 5, lane = threadIdx.x & 31;
    if (blockIdx.x == 96) {
        if (w == 0) {
            float s = 0.f;
            for (int c = lane; c < CC; c += 32) s += qb[c] * kb[c];
            #pragma unroll
            for (int o = 16; o; o >>= 1) s += __shfl_xor_sync(0xFFFFFFFFu, s, o);
            if (lane == 0) g_s0[0] = s;
        }
        return;
    }
    int j = blockIdx.x * 4 + w;
    float s = 0.f;
    for (int c = lane; c < CC; c += 32) s += pw[(size_t)j * CC + c] * vb[c];
    #pragma unroll
    for (int o = 16; o; o >>= 1) s += __shfl_xor_sync(0xFFFFFFFFu, s, o);
    if (lane == 0) g_pvb[j] = s;
}

// ---------------- generic 64x64-tile fp32 GEMM (K=C=384, N mult of 64) ----------------
// AM: 0 = A row-major A[i*C+k]; 1 = A k-major A[k*C+i]; 2 = row-major sum of NSEG partials
// BM: 0 = B k-major B[k*C+j];   1 = B n-major B[j*C+k]
// EPI:0 = store; 1 = +bias[j]; 2 = out epilogue ((v+cnt*pvb)/(cnt+1)+bias)
template<int AM, int BM, int EPI>
__global__ void __launch_bounds__(256) k_gemm64(const float* __restrict__ A,
                                                const float* __restrict__ Bm,
                                                float* __restrict__ Cc,
                                                const float* __restrict__ bias,
                                                const int* __restrict__ cnt,
                                                const float* __restrict__ pvb) {
    __shared__ float As[16][68];
    __shared__ float Bs[16][68];
    int j0 = blockIdx.x * 64, i0 = blockIdx.y * 64;
    int tid = threadIdx.x;
    float acc[4][4] = {};
    for (int k0 = 0; k0 < CC; k0 += 16) {
        // --- A tile: 64 i x 16 k ---
        if (AM == 1) {
            int kk = tid >> 4, i4 = (tid & 15) * 4;
            *(float4*)&As[kk][i4] = *(const float4*)&A[(size_t)(k0 + kk) * CC + i0 + i4];
        } else {
            int r = tid >> 2, kq = (tid & 3) * 4;
            float4 v;
            if (AM == 2) {
                const float* p = &A[(size_t)(i0 + r) * CC + k0 + kq];
                const size_t PS = (size_t)BB * GG * CC;
                float4 s = *(const float4*)p;
                #pragma unroll
                for (int q = 1; q < NSEG; q++) {
                    float4 vq = *(const float4*)(p + (size_t)q * PS);
                    s.x += vq.x; s.y += vq.y; s.z += vq.z; s.w += vq.w;
                }
                v = s;
            } else {
                v = *(const float4*)&A[(size_t)(i0 + r) * CC + k0 + kq];
            }
            As[kq + 0][r] = v.x; As[kq + 1][r] = v.y;
            As[kq + 2][r] = v.z; As[kq + 3][r] = v.w;
        }
        // --- B tile: 16 k x 64 j ---
        if (BM == 0) {
            int kk = tid >> 4, j4 = (tid & 15) * 4;
            *(float4*)&Bs[kk][j4] = *(const float4*)&Bm[(size_t)(k0 + kk) * CC + j0 + j4];
        } else {
            int jr = tid >> 2, kq = (tid & 3) * 4;
            float4 v = *(const float4*)&Bm[(size_t)(j0 + jr) * CC + k0 + kq];
            Bs[kq + 0][jr] = v.x; Bs[kq + 1][jr] = v.y;
            Bs[kq + 2][jr] = v.z; Bs[kq + 3][jr] = v.w;
        }
        __syncthreads();
        int ty = tid >> 4, tx = tid & 15;
        #pragma unroll
        for (int kk = 0; kk < 16; kk++) {
            float4 a4 = *(const float4*)&As[kk][ty * 4];
            float4 b4 = *(const float4*)&Bs[kk][tx * 4];
            float av[4] = {a4.x, a4.y, a4.z, a4.w};
            float bv[4] = {b4.x, b4.y, b4.z, b4.w};
            #pragma unroll
            for (int i = 0; i < 4; i++)
                #pragma unroll
                for (int j = 0; j < 4; j++)
                    acc[i][j] += av[i] * bv[j];
        }
        __syncthreads();
    }
    int ty = tid >> 4, tx = tid & 15;
    #pragma unroll
    for (int i = 0; i < 4; i++) {
        int r = i0 + ty * 4 + i;
        #pragma unroll
        for (int j = 0; j < 4; j++) {
            int c = j0 + tx * 4 + j;
            float v = acc[i][j];
            if (EPI == 1) v += bias[c];
            if (EPI == 2) {
                float cf = (float)cnt[r];
                v = (v + cf * pvb[c]) / (cf + 1.0f) + bias[c];
            }
            Cc[(size_t)r * CC + c] = v;
        }
    }
}

// ---------------- t[r] = query[r,:].u + s0 ----------------
__global__ void k_t(const float* __restrict__ query) {
    int r = blockIdx.x * 8 + threadIdx.y;
    int lane = threadIdx.x;
    float s = 0.f;
    for (int c = lane; c < CC; c += 32) s += query[(size_t)r * CC + c] * g_u[c];
    #pragma unroll
    for (int o = 16; o; o >>= 1) s += __shfl_xor_sync(0xFFFFFFFFu, s, o);
    if (lane == 0) g_t[r] = s + g_s0[0];
}

// ---------------- logits: L[b,g,n] = SCALE*(q2[b,g,:].key[b,n,:] + t[b,g]) ----------------
// 64(g) x 128(n) tile per block; 128 threads; 8x8 micro-tile; packed f32x2 FMA.
__global__ void __launch_bounds__(128) k_logits(const float* __restrict__ key,
                                                float* __restrict__ soft) {
    __shared__ float sA[16][72];
    __shared__ float sB[16][136];
    int b = blockIdx.y;
    int n_base = blockIdx.x * 128;
    int tid = threadIdx.x;
    const float* q2 = g_q2 + (size_t)b * GG * CC;
    const float* kp = key + ((size_t)b * NN + n_base) * CC;
    unsigned long long acc2[8][4];
    #pragma unroll
    for (int i = 0; i < 8; i++)
        #pragma unroll
        for (int j = 0; j < 4; j++) acc2[i][j] = 0ULL;

    for (int k0 = 0; k0 < CC; k0 += 16) {
        {   // A: 64g x 16k  (8 floats / thread)
            int g = tid >> 1, ks = (tid & 1) * 8;
            float4 v0 = *(const float4*)&q2[(size_t)g * CC + k0 + ks];
            float4 v1 = *(const float4*)&q2[(size_t)g * CC + k0 + ks + 4];
            sA[ks + 0][g] = v0.x; sA[ks + 1][g] = v0.y; sA[ks + 2][g] = v0.z; sA[ks + 3][g] = v0.w;
            sA[ks + 4][g] = v1.x; sA[ks + 5][g] = v1.y; sA[ks + 6][g] = v1.z; sA[ks + 7][g] = v1.w;
        }
        #pragma unroll
        for (int p = 0; p < 4; p++) {  // B: 128n x 16k (4 float4 / thread)
            int nn = (tid >> 2) + p * 32, kq = (tid & 3) * 4;
            float4 v = *(const float4*)&kp[(size_t)nn * CC + k0 + kq];
            sB[kq + 0][nn] = v.x; sB[kq + 1][nn] = v.y;
            sB[kq + 2][nn] = v.z; sB[kq + 3][nn] = v.w;
        }
        __syncthreads();
        int ty = tid >> 4, tx = tid & 15;
        #pragma unroll
        for (int kk = 0; kk < 16; kk++) {
            float a[8];
            *(float4*)&a[0] = *(const float4*)&sA[kk][ty * 8];
            *(float4*)&a[4] = *(const float4*)&sA[kk][ty * 8 + 4];
            ulonglong2 bb01 = *(const ulonglong2*)&sB[kk][tx * 8 + 0];
            ulonglong2 bb23 = *(const ulonglong2*)&sB[kk][tx * 8 + 4];
            unsigned long long b2[4] = {bb01.x, bb01.y, bb23.x, bb23.y};
            #pragma unroll
            for (int i = 0; i < 8; i++) {
                unsigned long long aa = pack2(a[i], a[i]);
                #pragma unroll
                for (int j = 0; j < 4; j++) fma_f32x2(acc2[i][j], aa, b2[j], acc2[i][j]);
            }
        }
        __syncthreads();
    }
    int ty = tid >> 4, tx = tid & 15;
    float* outp = soft + (size_t)b * GG * NN + n_base + tx * 8;
    #pragma unroll
    for (int i = 0; i < 8; i++) {
        int g = ty * 8 + i;
        float tb = g_t[b * GG + g];
        float o[8];
        #pragma unroll
        for (int j = 0; j < 4; j++) unpack2(o[2 * j], o[2 * j + 1], acc2[i][j]);
        #pragma unroll
        for (int j = 0; j < 8; j++) o[j] = SCALE * (o[j] + tb);
        *(float4*)&outp[(size_t)g * NN + 0] = *(float4*)&o[0];
        *(float4*)&outp[(size_t)g * NN + 4] = *(float4*)&o[4];
    }
}

// ---------------- column softmax over G, argmax, counts (in-place) ----------------
__global__ void k_softmax(float* __restrict__ soft, int* __restrict__ idx,
                          int* __restrict__ cnt) {
    int t = blockIdx.x * blockDim.x + threadIdx.x;  // over B*N
    int b = t >> 12, n = t & (NN - 1);
    float* col = soft + (size_t)b * GG * NN + n;
    float v[GG];
    float mx = -3.4e38f;
    int am = 0;
    #pragma unroll
    for (int g = 0; g < GG; g++) {
        v[g] = col[(size_t)g * NN];
        if (v[g] > mx) { mx = v[g]; am = g; }
    }
    float s = 0.f;
    #pragma unroll
    for (int g = 0; g < GG; g++) { v[g] = __expf(v[g] - mx); s += v[g]; }
    float inv = 1.0f / s;
    #pragma unroll
    for (int g = 0; g < GG; g++) col[(size_t)g * NN] = v[g] * inv;
    idx[t] = am;
    atomicAdd(&cnt[b * GG + am], 1);
}

// ---------------- segment sums of key rows by argmax group ----------------
__global__ void __launch_bounds__(128) k_seg(const float* __restrict__ key) {
    __shared__ float S[GG][128];
    __shared__ int sidx[512];
    int ns = blockIdx.x, cb = blockIdx.y, b = blockIdx.z;
    int tid = threadIdx.x;
    int c0 = cb * 128, nb = ns * 512;
    for (int i = tid; i < GG * 128; i += 128) ((float*)S)[i] = 0.f;
    for (int i = tid; i < 512; i += 128) sidx[i] = g_idx[b * NN + nb + i];
    __syncthreads();
    const float* kp = key + ((size_t)(b * NN + nb)) * CC + c0;
    for (int n = 0; n < 512; n += 8) {
        float x[8];
        #pragma unroll
        for (int i = 0; i < 8; i++) x[i] = kp[(size_t)(n + i) * CC + tid];
        #pragma unroll
        for (int i = 0; i < 8; i++) S[sidx[n + i]][tid] += x[i];
    }
    __syncthreads();
    float* dst = g_Sp + (size_t)ns * BB * GG * CC + (size_t)b * GG * CC + c0 + tid;
    for (int g = 0; g < GG; g++) dst[(size_t)g * CC] = S[g][tid];
}

// ---------------- launcher ----------------
extern "C" void kernel_launch(void* const* d_in, const int* in_sizes, int n_in,
                              void* d_out, int out_size) {
    const float* query = (const float*)d_in[0];
    const float* key   = (const float*)d_in[1];
    const float* q_w   = (const float*)d_in[2];
    const float* q_b   = (const float*)d_in[3];
    const float* k_w   = (const float*)d_in[4];
    const float* k_b   = (const float*)d_in[5];
    const float* v_w   = (const float*)d_in[6];
    const float* v_b   = (const float*)d_in[7];
    const float* p_w   = (const float*)d_in[8];
    const float* p_b   = (const float*)d_in[9];
    (void)v_w; (void)n_in; (void)in_sizes;

    float* out  = (float*)d_out;
    float* soft = out + ((size_t)out_size - (size_t)BB * GG * NN);

    float *pWq, *pMm, *pbq2, *pq2, *ppvb, *pSp;
    int *pidx, *pcnt;
    cudaGetSymbolAddress((void**)&pWq,  g_Wq);
    cudaGetSymbolAddress((void**)&pMm,  g_Mm);
    cudaGetSymbolAddress((void**)&pbq2, g_bq2);
    cudaGetSymbolAddress((void**)&pq2,  g_q2);
    cudaGetSymbolAddress((void**)&ppvb, g_pvb);
    cudaGetSymbolAddress((void**)&pSp,  g_Sp);
    cudaGetSymbolAddress((void**)&pidx, g_idx);
    cudaGetSymbolAddress((void**)&pcnt, g_cnt);

    // 1. zero counts
    k_zero<<<2, 1024>>>(pcnt);
    // 2. parallel precomputes
    k_prep_cols<<<12, CC>>>(q_w, q_b, k_w, k_b);
    k_prep_pv<<<97, 128>>>(p_w, v_b, q_b, k_b);
    k_prep_red<<<1, CC>>>();
    // 3. Wq = q_w.T @ k_w ; Mm = p_w @ v_w
    k_gemm64<1, 0, 0><<<dim3(6, 6), 256>>>(q_w, k_w, pWq, nullptr, nullptr, nullptr);
    k_gemm64<0, 0, 0><<<dim3(6, 6), 256>>>(p_w, d_in[6] ? (const float*)d_in[6] : nullptr, pMm, nullptr, nullptr, nullptr);
    // 4. t[r]
    k_t<<<BB * GG / 8, dim3(32, 8)>>>(query);
    // 5. q2 = query @ Wq + bq2
    k_gemm64<0, 0, 1><<<dim3(6, 32), 256>>>(query, pWq, pq2, pbq2, nullptr, nullptr);
    // 6. logits into soft region
    k_logits<<<dim3(NN / 128, BB), 128>>>(key, soft);
    // 7. softmax over G + argmax + counts (in place)
    k_softmax<<<BB * NN / 256, 256>>>(soft, pidx, pcnt);
    // 8. segment sums of key
    k_seg<<<dim3(NSEG, 3, BB), 128>>>(key);
    // 9. out = (S @ Mm.T + cnt*pvb)/(cnt+1) + p_b
    k_gemm64<2, 1, 2><<<dim3(6, 32), 256>>>(pSp, pMm, out, p_b, pcnt, ppvb);
}